// round 10
// baseline (speedup 1.0000x reference)
#include <cuda_runtime.h>
#include <math.h>
#include <stdint.h>

#define B  8
#define C  64
#define Hc 256
#define Wc 256
#define CR 128
#define HR 128
#define WR 128

__device__ float g_part[B * CR * 2];   // half-plane partial sums
__device__ int   g_idx[B * C];

// ---------------------------------------------------------------------------
// Kernel 1: per-batch analytic upsample-mean partials.
// grid = CR*2 (cr, half) for ONE batch; 8 float4 loads/thread.
// ---------------------------------------------------------------------------
__global__ void __launch_bounds__(256) scores_kernel(const float* __restrict__ readout,
                                                     int bofs) {
    __shared__ float wA[HR];
    __shared__ float red[8];
    const int tid = threadIdx.x;

    if (tid < HR) wA[tid] = 0.0f;
    __syncthreads();
    {
        const float cst = (float)(127.0 / 255.0);
        float pos = (float)tid * cst;
        int i0 = (int)pos;
        if (i0 > HR - 2) i0 = HR - 2;
        float w = pos - (float)i0;
        atomicAdd(&wA[i0], 1.0f - w);
        atomicAdd(&wA[i0 + 1], w);
    }
    __syncthreads();

    const int blk   = blockIdx.x;          // cr*2 + half
    const int cr    = blk >> 1;
    const int half  = blk & 1;
    const int plane = bofs * CR + cr;
    const float4* __restrict__ src =
        (const float4*)(readout + (size_t)plane * (HR * WR)) + half * 2048;

    float4 v[8];
    #pragma unroll
    for (int j = 0; j < 8; j++)
        v[j] = src[tid + j * 256];

    float acc0 = 0.f, acc1 = 0.f, acc2 = 0.f, acc3 = 0.f;
    #pragma unroll
    for (int j = 0; j < 8; j++) {
        int idx4 = half * 2048 + tid + j * 256;
        int row = idx4 >> 5;
        int col = (idx4 << 2) & 127;
        float wr = wA[row];
        float s = wA[col] * v[j].x + wA[col + 1] * v[j].y +
                  wA[col + 2] * v[j].z + wA[col + 3] * v[j].w;
        if (j == 0 || j == 4) acc0 += wr * s;
        else if (j == 1 || j == 5) acc1 += wr * s;
        else if (j == 2 || j == 6) acc2 += wr * s;
        else acc3 += wr * s;
    }

    float acc = (acc0 + acc1) + (acc2 + acc3);
    #pragma unroll
    for (int s = 16; s > 0; s >>= 1)
        acc += __shfl_down_sync(0xffffffffu, acc, s);
    if ((tid & 31) == 0) red[tid >> 5] = acc;
    __syncthreads();
    if (tid == 0) {
        float t = 0.f;
        #pragma unroll
        for (int w2 = 0; w2 < 8; w2++) t += red[w2];
        g_part[plane * 2 + half] = t;
    }
}

// ---------------------------------------------------------------------------
// Kernel 2: per-batch combine + descending bitonic sort (tie: lower index).
// ---------------------------------------------------------------------------
__global__ void topk_kernel(int bofs) {
    __shared__ float sv[CR];
    __shared__ int   si[CR];
    const int tid = threadIdx.x;
    const int b = bofs;

    const int p = b * CR + tid;
    sv[tid] = (g_part[2 * p] + g_part[2 * p + 1]) * (1.0f / (float)(Hc * Wc));
    si[tid] = tid;
    __syncthreads();

    for (int k = 2; k <= CR; k <<= 1) {
        for (int j = k >> 1; j > 0; j >>= 1) {
            int ixj = tid ^ j;
            if (ixj > tid) {
                float va = sv[tid], vb = sv[ixj];
                int   ia = si[tid], ib = si[ixj];
                bool first = (va > vb) || (va == vb && ia < ib);
                bool ascSeg = ((tid & k) == 0);
                bool doSwap = ascSeg ? (!first) : first;
                if (doSwap) {
                    sv[tid] = vb; sv[ixj] = va;
                    si[tid] = ib; si[ixj] = ia;
                }
            }
            __syncthreads();
        }
    }
    if (tid < C) g_idx[b * C + tid] = si[tid];
}

// ---------------------------------------------------------------------------
// Kernel 3: fused bilinear-upsample + gated blend (proven R4 body),
// restricted to one batch via bofs; blockIdx.z in [0, C).
// ---------------------------------------------------------------------------
__global__ void __launch_bounds__(256) fuse_kernel(
    const float* __restrict__ x,
    const float* __restrict__ readout,
    const float* __restrict__ weight,
    const float* __restrict__ bias,
    float* __restrict__ out,
    int bofs)
{
    __shared__ float srow[10 * WR];

    const int c = blockIdx.z;
    const int b = bofs;
    const int plane = b * C + c;
    const int ch = g_idx[plane];

    const float* __restrict__ rsrc =
        readout + ((size_t)b * CR + ch) * (HR * WR);

    const int y0 = blockIdx.y << 4;          // 16 rows per block
    const float cst = (float)(127.0 / 255.0);

    int iy_lo = (int)((float)y0 * cst);        if (iy_lo > HR - 2) iy_lo = HR - 2;
    int iy_hi = (int)((float)(y0 + 15) * cst); if (iy_hi > HR - 2) iy_hi = HR - 2;
    iy_hi += 1;
    const int nrows = iy_hi - iy_lo + 1;      // <= 10

    const int tid = threadIdx.x;

    // front-batched stage loads (up to 320 slots over 256 threads)
    const int nslots = nrows * 32;
    float4 sv0, sv1;
    const bool st0 = (tid < nslots);
    const bool st1 = (tid + 256 < nslots);
    if (st0)
        sv0 = __ldg((const float4*)(rsrc + (iy_lo + (tid >> 5)) * WR + ((tid & 31) << 2)));
    if (st1)
        sv1 = __ldg((const float4*)(rsrc + (iy_lo + ((tid + 256) >> 5)) * WR + (((tid + 256) & 31) << 2)));

    // front-batched x loads: 4 rows, dense float4 lanes
    const int tx = tid & 63;
    const int ty = tid >> 6;
    const int x0 = tx << 2;

    size_t o[4];
    float4 xv[4];
    #pragma unroll
    for (int r = 0; r < 4; r++) {
        int y = y0 + ty + (r << 2);
        o[r] = ((size_t)plane * Hc + y) * Wc + x0;
        xv[r] = __ldcs((const float4*)(x + o[r]));
    }

    if (st0) *(float4*)(srow + (tid >> 5) * WR + ((tid & 31) << 2)) = sv0;
    if (st1) *(float4*)(srow + ((tid + 256) >> 5) * WR + (((tid + 256) & 31) << 2)) = sv1;
    __syncthreads();

    const float w0 = __ldg(weight + 2 * c);
    const float w1 = __ldg(weight + 2 * c + 1);
    const float bs = __ldg(bias + c);

    int   ixA[4];
    float wxA[4];
    #pragma unroll
    for (int k = 0; k < 4; k++) {
        float posx = (float)(x0 + k) * cst;
        int ix0 = (int)posx;
        if (ix0 > WR - 2) ix0 = WR - 2;
        ixA[k] = ix0;
        wxA[k] = posx - (float)ix0;
    }

    #pragma unroll
    for (int r = 0; r < 4; r++) {
        const int y = y0 + ty + (r << 2);
        float posy = (float)y * cst;
        int iy0 = (int)posy;
        if (iy0 > HR - 2) iy0 = HR - 2;
        const float wy = posy - (float)iy0;
        const float wy0 = 1.0f - wy;

        const float* __restrict__ s0 = srow + (iy0 - iy_lo) * WR;
        const float* __restrict__ s1 = s0 + WR;

        float xs[4] = {xv[r].x, xv[r].y, xv[r].z, xv[r].w};
        float os[4];
        #pragma unroll
        for (int k = 0; k < 4; k++) {
            int ix0 = ixA[k];
            // reference order: interpolate along H first, then W
            float a  = s0[ix0]     * wy0 + s1[ix0]     * wy;
            float bb = s0[ix0 + 1] * wy0 + s1[ix0 + 1] * wy;
            float rv = a * (1.0f - wxA[k]) + bb * wxA[k];
            float t = xs[k] * w0 + rv * w1 + bs;
            float gate = 1.0f / (1.0f + __expf(-t));
            os[k] = xs[k] + gate * (rv - xs[k]);
        }
        __stcs((float4*)(out + o[r]), make_float4(os[0], os[1], os[2], os[3]));
    }
}

// ---------------------------------------------------------------------------
// Host: per-batch pipeline across two streams (fork/join via events).
// Stream2: scores(b) -> topk(b) -> record ev[b].  Main: wait ev[b] -> fuse(b).
// ---------------------------------------------------------------------------
extern "C" void kernel_launch(void* const* d_in, const int* in_sizes, int n_in,
                              void* d_out, int out_size)
{
    const float* x       = (const float*)d_in[0];
    const float* readout = (const float*)d_in[1];
    const float* weight  = (const float*)d_in[2];
    const float* bias    = (const float*)d_in[3];
    float* out = (float*)d_out;

    static cudaStream_t s2 = 0;
    static cudaEvent_t evF = 0;
    static cudaEvent_t evB[B];
    static bool inited = false;
    if (!inited) {
        if (cudaStreamCreateWithFlags(&s2, cudaStreamNonBlocking) != cudaSuccess)
            s2 = 0;  // fallback: everything on default stream, same work
        cudaEventCreateWithFlags(&evF, cudaEventDisableTiming);
        for (int b = 0; b < B; b++)
            cudaEventCreateWithFlags(&evB[b], cudaEventDisableTiming);
        inited = true;
    }

    cudaStream_t sAux = s2 ? s2 : 0;

    // fork: aux stream joins behind whatever precedes us on the main stream
    cudaEventRecord(evF, 0);
    if (s2) cudaStreamWaitEvent(sAux, evF, 0);

    for (int b = 0; b < B; b++) {
        scores_kernel<<<CR * 2, 256, 0, sAux>>>(readout, b);
        topk_kernel<<<1, CR, 0, sAux>>>(b);
        cudaEventRecord(evB[b], sAux);
    }

    dim3 blk(256, 1, 1);
    dim3 grd(1, Hc / 16, C);   // 1024 blocks per batch
    for (int b = 0; b < B; b++) {
        if (s2) cudaStreamWaitEvent(0, evB[b], 0);
        fuse_kernel<<<grd, blk>>>(x, readout, weight, bias, out, b);
    }
}